// round 14
// baseline (speedup 1.0000x reference)
#include <cuda_runtime.h>
#include <cuda_fp16.h>
#include <cstdint>
#include <math.h>

#define NB   4
#define SEQ  4096
#define EMB  1024
#define HID  4096
#define NTOK (NB * SEQ)   // 16384

// ======================= helpers ==============================================
__device__ __forceinline__ uint32_t smem_u32(const void* p) {
    uint32_t a;
    asm("{ .reg .u64 t; cvta.to.shared.u64 t, %1; cvt.u32.u64 %0, t; }" : "=r"(a) : "l"(p));
    return a;
}
__device__ __forceinline__ void cp_async16(uint32_t dst, const void* src) {
    asm volatile("cp.async.cg.shared.global [%0], [%1], 16;" :: "r"(dst), "l"(src));
}
#define CP_COMMIT() asm volatile("cp.async.commit_group;" ::: "memory")
#define CP_WAIT2()  asm volatile("cp.async.wait_group 2;" ::: "memory")
#define CP_WAIT0()  asm volatile("cp.async.wait_group 0;" ::: "memory")

__device__ __forceinline__ void ldmx4(uint32_t r[4], uint32_t addr) {
    asm volatile("ldmatrix.sync.aligned.m8n8.x4.shared.b16 {%0,%1,%2,%3}, [%4];"
                 : "=r"(r[0]), "=r"(r[1]), "=r"(r[2]), "=r"(r[3]) : "r"(addr));
}
__device__ __forceinline__ void mma16816(float d[4], const uint32_t a[4],
                                         uint32_t b0, uint32_t b1) {
    asm volatile("mma.sync.aligned.m16n8k16.row.col.f32.f16.f16.f32 "
                 "{%0,%1,%2,%3}, {%4,%5,%6,%7}, {%8,%9}, {%0,%1,%2,%3};"
                 : "+f"(d[0]), "+f"(d[1]), "+f"(d[2]), "+f"(d[3])
                 : "r"(a[0]), "r"(a[1]), "r"(a[2]), "r"(a[3]), "r"(b0), "r"(b1));
}
// 128-byte-row swizzle: granule (16B) index xor'ed with row&7 (classic SW128)
__device__ __forceinline__ uint32_t swz128r(int row, int kb) {
    return (uint32_t)(row * 128 + ((((kb) >> 4) ^ (row & 7)) << 4));
}

// ======================= device scratch =======================================
__device__ float g_wvs [EMB * 64];
__device__ __align__(16) __half g_vsh [EMB * EMB];              // vsum fp16 (1024x1024 view)
__device__ __align__(16) __half g_woT [EMB * EMB];              // w_o^T fp16
__device__ float g_A   [NB * 256 * EMB];
__device__ float g_h1  [(long long)NTOK * EMB];                 // fp32 residual
__device__ __align__(16) __half g_h1f [(long long)NTOK * EMB];  // h1 fp16
__device__ __align__(16) __half g_ff1 [(long long)NTOK * HID];  // relu(ff1) fp16
__device__ __align__(16) __half g_w1t [(long long)HID * EMB];   // w_ff1^T fp16
__device__ __align__(16) __half g_w2t [(long long)EMB * HID];   // w_ff2^T fp16
__device__ float g_y   [(long long)NTOK * EMB];

// ======================= fold w_v over heads ==================================
__global__ void fold_wv_kernel(const float* __restrict__ wv) {
    int idx = blockIdx.x * blockDim.x + threadIdx.x;
    if (idx >= EMB * 64) return;
    int e = idx >> 6, d = idx & 63;
    float s = 0.f;
#pragma unroll
    for (int j = 0; j < 16; j++) s += wv[e * EMB + j * 64 + d];
    g_wvs[idx] = s;
}

// ============== transpose + fp16 convert: src(R,C) -> dst(C,R) ================
__global__ void transpose_cvt(const float* __restrict__ src,
                              __half* __restrict__ dst, int R, int C) {
    __shared__ float tile[32][33];
    int r = blockIdx.y * 32 + threadIdx.y;
    int c = blockIdx.x * 32 + threadIdx.x;
    tile[threadIdx.y][threadIdx.x] = src[(size_t)r * C + c];
    __syncthreads();
    int orow = blockIdx.x * 32 + threadIdx.y;
    int ocol = blockIdx.y * 32 + threadIdx.x;
    dst[(size_t)orow * R + ocol] = __float2half(tile[threadIdx.x][threadIdx.y]);
}

// ====== Vsum = x @ Wvs : (16384,1024)@(1024,64), fp16 out =====================
__global__ __launch_bounds__(256)
void vsum_kernel(const float* __restrict__ x) {
    __shared__ float  As[32][33];
    __shared__ float4 Bs[32][16];
    const int tid = threadIdx.x;
    const int base = blockIdx.x * 32;
    const int tx = tid & 15, ty = tid >> 4;
    float acc[2][4] = {};
    const int lr = tid >> 3, lc4 = (tid & 7) * 4;
    for (int k0 = 0; k0 < EMB; k0 += 32) {
        float4 a4 = *(const float4*)(x + (size_t)(base + lr) * EMB + k0 + lc4);
        As[lr][lc4 + 0] = a4.x; As[lr][lc4 + 1] = a4.y;
        As[lr][lc4 + 2] = a4.z; As[lr][lc4 + 3] = a4.w;
#pragma unroll
        for (int i = 0; i < 2; i++) {
            int f = tid * 2 + i;
            int row = f >> 4, col4 = f & 15;
            Bs[row][col4] = ((const float4*)g_wvs)[(size_t)(k0 + row) * 16 + col4];
        }
        __syncthreads();
#pragma unroll
        for (int ks = 0; ks < 32; ks++) {
            float a0 = As[ty * 2 + 0][ks];
            float a1 = As[ty * 2 + 1][ks];
            float4 b4 = Bs[ks][tx];
            acc[0][0] += a0 * b4.x; acc[0][1] += a0 * b4.y;
            acc[0][2] += a0 * b4.z; acc[0][3] += a0 * b4.w;
            acc[1][0] += a1 * b4.x; acc[1][1] += a1 * b4.y;
            acc[1][2] += a1 * b4.z; acc[1][3] += a1 * b4.w;
        }
        __syncthreads();
    }
#pragma unroll
    for (int i = 0; i < 2; i++) {
        const size_t o = (size_t)(base + ty * 2 + i) * 64 + tx * 4;
        __align__(8) __half h4[4];
        h4[0] = __float2half(acc[i][0]); h4[1] = __float2half(acc[i][1]);
        h4[2] = __float2half(acc[i][2]); h4[3] = __float2half(acc[i][3]);
        *(uint2*)(g_vsh + o) = *(uint2*)h4;
    }
}

// ================= HMMA fp16 GEMM =============================================
// C = A(M,K) @ B(N,K)^T, fp16 in, fp32 accum. CTA tile 128x128xK64,
// 8 warps (2x4 grid), warp tile 64x32, 256 threads (R6 geometry).
// K-chunk 64 (4 k16 steps per chunk): half the barriers/pipeline restarts of
// the 32-chunk version. 3-stage ring, 32KB/stage (128B rows, SW128 row-xor
// swizzle), 96KB total -> 2 CTAs/SM. Tail uses wait_group 0 (race-safe).
// G1: out = relu(C+bias) -> fp16.  !G1: out = C+bias (+res if RES) -> fp32.
#define STG_BYTES 32768
#define N_STAGES  3
template <bool G1, bool RES>
__global__ __launch_bounds__(256)
void gemm_mma(const __half* __restrict__ A, const __half* __restrict__ B,
              const float* __restrict__ bias, const float* __restrict__ res,
              __half* __restrict__ Oh, float* __restrict__ Of, int K, int N) {
    extern __shared__ char smem[];
    const uint32_t sb = smem_u32(smem);
    const int tid  = threadIdx.x;
    const int lane = tid & 31;
    const int wid  = tid >> 5;
    const int wm = wid >> 2;          // 0..1  (64-row slab)
    const int wn = wid & 3;           // 0..3  (32-col slab)
    const int bx = blockIdx.x, by = blockIdx.y;

    // ---- loader mapping: 256 threads, each 4x16B (=64B contiguous) per array -
    const int lrow = tid >> 1;            // 0..127
    const int g2   = (tid & 1) * 4;       // granule base 0 or 4
    uint32_t sdA[4];
#pragma unroll
    for (int i = 0; i < 4; i++)
        sdA[i] = (uint32_t)(lrow * 128 + (((g2 + i) ^ (lrow & 7)) << 4));
    const size_t arow = (size_t)(by * 128 + lrow) * K;
    const size_t brow = (size_t)(bx * 128 + lrow) * K;

    const int NC = K / 64;
    auto load_stage = [&](int c, int s) {
        const uint32_t st = sb + s * STG_BYTES;
        const int kc = c * 64;
#pragma unroll
        for (int i = 0; i < 4; i++)
            cp_async16(st + sdA[i], A + arow + kc + (g2 + i) * 8);
#pragma unroll
        for (int i = 0; i < 4; i++)
            cp_async16(st + 16384 + sdA[i], B + brow + kc + (g2 + i) * 8);
        CP_COMMIT();
    };

    // prologue: fill all 3 slots
    load_stage(0, 0); load_stage(1, 1); load_stage(2, 2);

    // ---- ldmatrix lane addressing -------------------------------------------
    const int lr8 = lane & 7, l8 = (lane >> 3) & 1, l16 = (lane >> 4) & 1;
    const int frow = lr8 + l8 * 8;        // row within 16-row tile
    const int fkb  = l16 * 16;            // 0 or 16 bytes within k16 step

    float acc[4][4][4] = {};

    for (int c = 0; c < NC; c++) {
        const int s = c % N_STAGES;
        if (c < NC - 2) CP_WAIT2(); else CP_WAIT0();
        __syncthreads();
        const uint32_t st = sb + s * STG_BYTES;
#pragma unroll
        for (int ks = 0; ks < 4; ks++) {
            const int kb = ks * 32 + fkb;
            uint32_t ah[4][4], b[4][2];
#pragma unroll
            for (int mi = 0; mi < 4; mi++)
                ldmx4(ah[mi], st + swz128r(wm * 64 + mi * 16 + frow, kb));
#pragma unroll
            for (int nt = 0; nt < 2; nt++) {
                uint32_t q[4];
                ldmx4(q, st + 16384 + swz128r(wn * 32 + nt * 16 + frow, kb));
                b[nt*2][0] = q[0]; b[nt*2+1][0] = q[1];
                b[nt*2][1] = q[2]; b[nt*2+1][1] = q[3];
            }
#pragma unroll
            for (int mi = 0; mi < 4; mi++)
#pragma unroll
                for (int j = 0; j < 4; j++)
                    mma16816(acc[mi][j], ah[mi], b[j][0], b[j][1]);
        }
        __syncthreads();
        if (c + 3 < NC) load_stage(c + 3, s);
    }

    // ---- epilogue ------------------------------------------------------------
    const int g = lane >> 2, tg = lane & 3;
#pragma unroll
    for (int mi = 0; mi < 4; mi++) {
#pragma unroll
        for (int j = 0; j < 4; j++) {
            const int col = bx * 128 + wn * 32 + j * 8 + tg * 2;
            const float2 b2 = *(const float2*)(bias + col);
#pragma unroll
            for (int hrow = 0; hrow < 2; hrow++) {
                const size_t row = (size_t)(by * 128 + wm * 64 + mi * 16 + g + hrow * 8);
                float v0 = acc[mi][j][hrow * 2 + 0] + b2.x;
                float v1 = acc[mi][j][hrow * 2 + 1] + b2.y;
                if (G1) {
                    v0 = fmaxf(v0, 0.f); v1 = fmaxf(v1, 0.f);
                    __half2 hh;
                    hh.x = __float2half(v0); hh.y = __float2half(v1);
                    *(__half2*)(Oh + row * N + col) = hh;
                } else {
                    float2 o = make_float2(v0, v1);
                    if (RES) {
                        const float2 rv = *(const float2*)(res + row * N + col);
                        o.x += rv.x; o.y += rv.y;
                    }
                    *(float2*)(Of + row * N + col) = o;
                }
            }
        }
    }
}

// ======================= LayerNorm kernels ====================================
__device__ __forceinline__ void block_reduce2(float& s, float& q) {
#pragma unroll
    for (int off = 16; off; off >>= 1) {
        s += __shfl_xor_sync(0xffffffffu, s, off);
        q += __shfl_xor_sync(0xffffffffu, q, off);
    }
    __shared__ float sh_s[8], sh_q[8];
    int w = threadIdx.x >> 5;
    if ((threadIdx.x & 31) == 0) { sh_s[w] = s; sh_q[w] = q; }
    __syncthreads();
    s = 0.f; q = 0.f;
#pragma unroll
    for (int i = 0; i < 8; i++) { s += sh_s[i]; q += sh_q[i]; }
}

__global__ void ln1_kernel(const float* __restrict__ x,
                           const float* __restrict__ w, const float* __restrict__ b) {
    int t = blockIdx.x;
    int n = t >> 12, l = t & (SEQ - 1);
    int c = threadIdx.x;
    float4 xv = ((const float4*)(x + (size_t)t * EMB))[c];
    float4 av = ((const float4*)(g_A + (size_t)(n * 256 + (l & 255)) * EMB))[c];
    float v0 = xv.x + av.x, v1 = xv.y + av.y, v2 = xv.z + av.z, v3 = xv.w + av.w;
    float s = v0 + v1 + v2 + v3;
    float q = v0 * v0 + v1 * v1 + v2 * v2 + v3 * v3;
    block_reduce2(s, q);
    float mu  = s * (1.f / EMB);
    float var = q * (1.f / EMB) - mu * mu;
    float rs  = rsqrtf(var + 1e-5f);
    float4 wv = ((const float4*)w)[c], bv = ((const float4*)b)[c];
    float4 o;
    o.x = (v0 - mu) * rs * wv.x + bv.x;
    o.y = (v1 - mu) * rs * wv.y + bv.y;
    o.z = (v2 - mu) * rs * wv.z + bv.z;
    o.w = (v3 - mu) * rs * wv.w + bv.w;
    ((float4*)(g_h1 + (size_t)t * EMB))[c] = o;
    __align__(8) __half h4[4];
    h4[0] = __float2half(o.x); h4[1] = __float2half(o.y);
    h4[2] = __float2half(o.z); h4[3] = __float2half(o.w);
    ((uint2*)(g_h1f + (size_t)t * EMB))[c] = *(uint2*)h4;
}

__global__ void ln2_kernel(const float* __restrict__ w, const float* __restrict__ b,
                           float* __restrict__ out) {
    int t = blockIdx.x;
    int c = threadIdx.x;
    float4 yv = ((const float4*)(g_y + (size_t)t * EMB))[c];
    float v0 = yv.x, v1 = yv.y, v2 = yv.z, v3 = yv.w;
    float s = v0 + v1 + v2 + v3;
    float q = v0 * v0 + v1 * v1 + v2 * v2 + v3 * v3;
    block_reduce2(s, q);
    float mu  = s * (1.f / EMB);
    float var = q * (1.f / EMB) - mu * mu;
    float rs  = rsqrtf(var + 1e-5f);
    float4 wv = ((const float4*)w)[c], bv = ((const float4*)b)[c];
    float4 o;
    o.x = (v0 - mu) * rs * wv.x + bv.x;
    o.y = (v1 - mu) * rs * wv.y + bv.y;
    o.z = (v2 - mu) * rs * wv.z + bv.z;
    o.w = (v3 - mu) * rs * wv.w + bv.w;
    ((float4*)(out + (size_t)t * EMB))[c] = o;
}

// ==============================================================================
extern "C" void kernel_launch(void* const* d_in, const int* in_sizes, int n_in,
                              void* d_out, int out_size) {
    const float* x     = (const float*)d_in[0];
    const float* w_v   = (const float*)d_in[3];
    const float* w_o   = (const float*)d_in[4];
    const float* b_o   = (const float*)d_in[5];
    const float* ln1_w = (const float*)d_in[6];
    const float* ln1_b = (const float*)d_in[7];
    const float* ln2_w = (const float*)d_in[8];
    const float* ln2_b = (const float*)d_in[9];
    const float* w_ff1 = (const float*)d_in[10];
    const float* b_ff1 = (const float*)d_in[11];
    const float* w_ff2 = (const float*)d_in[12];
    const float* b_ff2 = (const float*)d_in[13];
    float* out = (float*)d_out;

    float *A, *h1, *y;
    __half *vsh, *woT, *h1f, *ff1, *w1t, *w2t;
    cudaGetSymbolAddress((void**)&A,   g_A);
    cudaGetSymbolAddress((void**)&h1,  g_h1);
    cudaGetSymbolAddress((void**)&y,   g_y);
    cudaGetSymbolAddress((void**)&vsh, g_vsh);
    cudaGetSymbolAddress((void**)&woT, g_woT);
    cudaGetSymbolAddress((void**)&h1f, g_h1f);
    cudaGetSymbolAddress((void**)&ff1, g_ff1);
    cudaGetSymbolAddress((void**)&w1t, g_w1t);
    cudaGetSymbolAddress((void**)&w2t, g_w2t);

    const int GEMM_SMEM = N_STAGES * STG_BYTES;   // 96 KB
    cudaFuncSetAttribute(gemm_mma<true,false>,  cudaFuncAttributeMaxDynamicSharedMemorySize, GEMM_SMEM);
    cudaFuncSetAttribute(gemm_mma<false,true>,  cudaFuncAttributeMaxDynamicSharedMemorySize, GEMM_SMEM);
    cudaFuncSetAttribute(gemm_mma<false,false>, cudaFuncAttributeMaxDynamicSharedMemorySize, GEMM_SMEM);

    // 1) prep: fold w_v; transpose+convert weights to K-major fp16
    fold_wv_kernel<<<(EMB * 64 + 255) / 256, 256>>>(w_v);
    transpose_cvt<<<dim3(EMB / 32, EMB / 32), dim3(32, 32)>>>(w_o,   woT, EMB, EMB);
    transpose_cvt<<<dim3(HID / 32, EMB / 32), dim3(32, 32)>>>(w_ff1, w1t, EMB, HID);
    transpose_cvt<<<dim3(EMB / 32, HID / 32), dim3(32, 32)>>>(w_ff2, w2t, HID, EMB);

    // 2) Vsum = x @ Wvs -> fp16 (1024x1024 view)
    vsum_kernel<<<NTOK / 32, 256>>>(x);

    // 3) A = Vsum @ w_o + b_o   [HMMA fp16]
    gemm_mma<false,false><<<dim3(EMB / 128, EMB / 128), 256, GEMM_SMEM>>>(
        vsh, woT, b_o, nullptr, nullptr, A, EMB, EMB);

    // 4) h1 = LN1(x + A[n, l%256])  (+ fp16 copy)
    ln1_kernel<<<NTOK, 256>>>(x, ln1_w, ln1_b);

    // 5) ff1 = relu(h1 @ w_ff1 + b_ff1) -> fp16   [HMMA fp16]
    gemm_mma<true,false><<<dim3(HID / 128, NTOK / 128), 256, GEMM_SMEM>>>(
        h1f, w1t, b_ff1, nullptr, ff1, nullptr, EMB, HID);

    // 6) y = ff1 @ w_ff2 + b_ff2 + h1 -> fp32      [HMMA fp16]
    gemm_mma<false,true><<<dim3(EMB / 128, NTOK / 128), 256, GEMM_SMEM>>>(
        ff1, w2t, b_ff2, h1, nullptr, y, HID, EMB);

    // 7) out = LN2(y)
    ln2_kernel<<<NTOK, 256>>>(ln2_w, ln2_b, out);
}